// round 9
// baseline (speedup 1.0000x reference)
#include <cuda_runtime.h>
#include <cstdint>

#define NB 32
#define NS 512
#define NI 128
#define NH 128
#define NO 32
#define G3 384
#define NJAC 116            // jacobian/ih blocks
#define NBLK (NB + NJAC)    // 148 total, 1 per SM

typedef unsigned long long u64;

// ---------------- scratch (static device globals) -----------------------------
__device__ float  g_ih[(size_t)NS * NB * G3];       // ih[s][b][g]
__device__ float4 g_coef[(size_t)NS * NB * NH];     // {cR,cN,cZ,z} per (t,b,j)
__device__ float  g_WrT[NH * NH];
__device__ float  g_WnT[NH * NH];
__device__ float  g_WzT[NH * NH];
__device__ int    g_prog[NB];                       // scan progress per batch
__device__ int    g_ihdone;                         // # ih blocks finished

// ---------------- helpers ------------------------------------------------------
__device__ __forceinline__ u64 pk2(float x, float y) {
    u64 r; asm("mov.b64 %0, {%1,%2};" : "=l"(r) : "f"(x), "f"(y)); return r;
}
__device__ __forceinline__ float2 up2(u64 v) {
    float2 r; asm("mov.b64 {%0,%1}, %2;" : "=f"(r.x), "=f"(r.y) : "l"(v)); return r;
}
__device__ __forceinline__ void fma2(u64 &d, u64 a, u64 b) {
    asm("fma.rn.f32x2 %0, %1, %2, %0;" : "+l"(d) : "l"(a), "l"(b));
}
__device__ __forceinline__ u64 mul2(u64 a, u64 b) {
    u64 d; asm("mul.rn.f32x2 %0, %1, %2;" : "=l"(d) : "l"(a), "l"(b)); return d;
}
__device__ __forceinline__ void lds128(u64 &a, u64 &b, const void* p) {
    unsigned addr = (unsigned)__cvta_generic_to_shared(p);
    asm volatile("ld.shared.v2.b64 {%0,%1}, [%2];" : "=l"(a), "=l"(b) : "r"(addr));
}
__device__ __forceinline__ int lda(const int* p) {   // acquire load, gpu scope
    int v; asm volatile("ld.acquire.gpu.global.s32 %0, [%1];" : "=r"(v) : "l"(p) : "memory");
    return v;
}
__device__ __forceinline__ void stv(int* p, int v) {
    asm volatile("st.volatile.global.s32 [%0], %1;" :: "l"(p), "r"(v) : "memory");
}
__device__ __forceinline__ float sigm(float x) {
    return __fdividef(1.f, 1.f + __expf(-x));        // rcp.approx path, no div.rn
}
__device__ __forceinline__ float tanh_fast(float a) {
    float ac = fminf(fmaxf(a, -15.f), 15.f);
    float e2 = __expf(2.f * ac);
    return 1.f - __fdividef(2.f, e2 + 1.f);
}

// ---------------- K0: transpose W_hh + reset sync state ------------------------
__global__ void k_prep(const float* __restrict__ W_hh) {
    int idx = blockIdx.x * blockDim.x + threadIdx.x;
    if (idx < 3 * NH * NH) {
        int m = idx / (NH * NH);
        int rem = idx - m * (NH * NH);
        int i = rem >> 7, j = rem & 127;
        int srcRow = (m == 0) ? j : ((m == 1) ? (2 * NH + j) : (NH + j));
        float v = W_hh[(size_t)srcRow * NH + i];
        if (m == 0)      g_WrT[rem] = v;
        else if (m == 1) g_WnT[rem] = v;
        else             g_WzT[rem] = v;
    } else {
        int k = idx - 3 * NH * NH;
        if (k < NB) g_prog[k] = 0;
        else if (k == NB) g_ihdone = 0;
    }
}

// ---------------- fused persistent kernel --------------------------------------
extern __shared__ float dynsm[];   // 192KB: WrT | WnT | WzT (jac blocks only)

__global__ void __launch_bounds__(384, 1)
k_fused(const float* __restrict__ x,
        const float* __restrict__ W_ih, const float* __restrict__ b_ih,
        const float* __restrict__ W_hh, const float* __restrict__ b_hh,
        const float* __restrict__ W_y,  const float* __restrict__ b_y,
        float* __restrict__ out) {
    __shared__ __align__(16) float sh_h[NH];
    __shared__ float sh_z[NH];
    __shared__ float sh_M[NH];
    __shared__ float sh_in[NH];
    __shared__ __align__(16) float sx[NI];

    int g = threadIdx.x;

    if (blockIdx.x < NB) {
        // ================= SCAN path: one block per batch ======================
        int b = blockIdx.x;
        u64 w[64];
        const float2* wrow = (const float2*)(W_hh + (size_t)g * NH);
#pragma unroll
        for (int k = 0; k < 64; k++) { float2 v = wrow[k]; w[k] = pk2(v.x, v.y); }
        float bias = b_hh[g];

        if (g < NH) sh_h[g] = 0.f;
        // single wait: all ih rows ready (acquire makes them visible)
        if (g == 0) { while (lda(&g_ihdone) < NJAC) __nanosleep(128); }
        __syncthreads();

        const float* ihp = g_ih + (size_t)b * G3 + g;
        float4* coefp = g_coef + (size_t)b * NH;

        for (int t = 0; t < NS; t++) {
            float ihv = __ldcg(ihp + (size_t)t * NB * G3);
            u64 a0 = 0ull, a1 = 0ull, a2 = 0ull, a3 = 0ull;
#pragma unroll
            for (int k = 0; k < 16; k++) {
                u64 h0, h1, h2, h3;
                lds128(h0, h1, &sh_h[8 * k]);
                lds128(h2, h3, &sh_h[8 * k + 4]);
                fma2(a0, w[4 * k + 0], h0);
                fma2(a1, w[4 * k + 1], h1);
                fma2(a2, w[4 * k + 2], h2);
                fma2(a3, w[4 * k + 3], h3);
            }
            float2 f0 = up2(a0), f1 = up2(a1), f2 = up2(a2), f3 = up2(a3);
            float hh = ((f0.x + f0.y) + (f1.x + f1.y)) + ((f2.x + f2.y) + (f3.x + f3.y)) + bias;
            float pre = ihv + hh;

            float r_local = 0.f;
            if (g < NH) {
                r_local = sigm(pre);
            } else if (g < 2 * NH) {
                sh_z[g - NH] = sigm(pre);
            } else {
                sh_M[g - 2 * NH]  = hh;
                sh_in[g - 2 * NH] = ihv;
            }
            __syncthreads();

            if (g < NH) {
                float r = r_local;
                float z = sh_z[g];
                float M = sh_M[g];
                float n = tanh_fast(sh_in[g] + r * M);
                float hp = sh_h[g];
                float hn = (1.f - z) * n + z * hp;
                sh_h[g] = hn;
                float c67 = (1.f - n * n) * (1.f - z);
                float4 c;
                c.x = r * (1.f - r) * M * c67;
                c.y = r * c67;
                c.z = z * (1.f - z) * (hp - n);
                c.w = z;
                coefp[(size_t)t * NB * NH + g] = c;
            }
            __syncthreads();
            if ((t & 1) && g == 0) {          // publish coefs for steps <= t
                __threadfence();              // cumulative gpu fence orders coef STGs
                stv(g_prog + b, t + 1);
            }
        }

        if (g < NO) {
            const float* wy = W_y + (size_t)g * NH;
            float acc = b_y[g];
#pragma unroll 8
            for (int j = 0; j < NH; j++) acc += wy[j] * sh_h[j];
            out[(size_t)b * NO + g] = acc;
        }
        return;
    }

    // ================= IH + JAC path (116 blocks) ==============================
    int jid = blockIdx.x - NB;
    float* sWr = dynsm;
    float* sWn = dynsm + 16384;
    float* sWz = dynsm + 32768;

    for (int k = g; k < NH * NH; k += 384) {
        sWr[k] = g_WrT[k];
        sWn[k] = g_WnT[k];
        sWz[k] = g_WzT[k];
    }
    __syncthreads();

    // ---- phase 1: ih = x @ W_ih^T + b_ih  (producer for scan) ----
    {
        u64 w[64];
        const float2* wrow = (const float2*)(W_ih + (size_t)g * NI);
#pragma unroll
        for (int k = 0; k < 64; k++) { float2 v = wrow[k]; w[k] = pk2(v.x, v.y); }
        float bias = b_ih[g];

        for (int p = jid; p < NS * NB; p += NJAC) {
            int s = p >> 5, b = p & 31;
            if (g < 32)
                ((float4*)sx)[g] = ((const float4*)(x + ((size_t)b * NS + s) * NI))[g];
            __syncthreads();
            u64 a0 = 0ull, a1 = 0ull, a2 = 0ull, a3 = 0ull;
#pragma unroll
            for (int k = 0; k < 16; k++) {
                u64 h0, h1, h2, h3;
                lds128(h0, h1, &sx[8 * k]);
                lds128(h2, h3, &sx[8 * k + 4]);
                fma2(a0, w[4 * k + 0], h0);
                fma2(a1, w[4 * k + 1], h1);
                fma2(a2, w[4 * k + 2], h2);
                fma2(a3, w[4 * k + 3], h3);
            }
            float2 f0 = up2(a0), f1 = up2(a1), f2 = up2(a2), f3 = up2(a3);
            float dot = ((f0.x + f0.y) + (f1.x + f1.y)) + ((f2.x + f2.y) + (f3.x + f3.y));
            g_ih[((size_t)s * NB + b) * G3 + g] = dot + bias;
            __syncthreads();
        }
        __syncthreads();
        if (g == 0) { __threadfence(); atomicAdd(&g_ihdone, 1); }
    }

    // ---- phase 2: jacobian, warp-autonomous, 2 tiles per W-row load ----
    {
        int l = g & 31, w = g >> 5;          // 12 warps/block
        int wg = jid * 12 + w;               // 0..1391
        const int NPAIR = NS * NB / 2;       // 8192 pairs

        for (int pr = wg; pr < NPAIR; pr += NJAC * 12) {
            int t  = pr >> 4;                // 16 pairs per t
            int b0 = (pr & 15) << 1;         // batches b0, b0+1

            int need = t + 1;
            while (lda(g_prog + b0)     < need) __nanosleep(64);
            while (lda(g_prog + b0 + 1) < need) __nanosleep(64);

            size_t q0 = (size_t)t * NB + b0;
            const float4* cpA = g_coef + q0 * NH + 4 * l;
            const float4* cpB = cpA + NH;
            float4 a0c = __ldcg(cpA + 0), a1c = __ldcg(cpA + 1);
            float4 a2c = __ldcg(cpA + 2), a3c = __ldcg(cpA + 3);
            float4 e0c = __ldcg(cpB + 0), e1c = __ldcg(cpB + 1);
            float4 e2c = __ldcg(cpB + 2), e3c = __ldcg(cpB + 3);

            u64 Acr01 = pk2(a0c.x, a1c.x), Acr23 = pk2(a2c.x, a3c.x);
            u64 Acn01 = pk2(a0c.y, a1c.y), Acn23 = pk2(a2c.y, a3c.y);
            u64 Acz01 = pk2(a0c.z, a1c.z), Acz23 = pk2(a2c.z, a3c.z);
            u64 Bcr01 = pk2(e0c.x, e1c.x), Bcr23 = pk2(e2c.x, e3c.x);
            u64 Bcn01 = pk2(e0c.y, e1c.y), Bcn23 = pk2(e2c.y, e3c.y);
            u64 Bcz01 = pk2(e0c.z, e1c.z), Bcz23 = pk2(e2c.z, e3c.z);
            float Az0 = a0c.w, Az1 = a1c.w, Az2 = a2c.w, Az3 = a3c.w;
            float Bz0 = e0c.w, Bz1 = e1c.w, Bz2 = e2c.w, Bz3 = e3c.w;

            float* oA = out + 1024 + ((size_t)(NS - 1 - t) * NB + b0) * (NH * NH) + 4 * l;
            float* oB = oA + NH * NH;

#pragma unroll 4
            for (int i = 0; i < NH; i++) {
                int idx = i * NH + 4 * l;
                u64 wr0, wr1, wn0, wn1, wz0, wz1;
                lds128(wr0, wr1, &sWr[idx]);
                lds128(wn0, wn1, &sWn[idx]);
                lds128(wz0, wz1, &sWz[idx]);

                u64 A01 = mul2(wr0, Acr01); fma2(A01, wn0, Acn01); fma2(A01, wz0, Acz01);
                u64 A23 = mul2(wr1, Acr23); fma2(A23, wn1, Acn23); fma2(A23, wz1, Acz23);
                u64 B01 = mul2(wr0, Bcr01); fma2(B01, wn0, Bcn01); fma2(B01, wz0, Bcz01);
                u64 B23 = mul2(wr1, Bcr23); fma2(B23, wn1, Bcn23); fma2(B23, wz1, Bcz23);

                if ((i >> 2) == l) {         // diagonal j == i in this lane
                    int d = i & 3;
                    if (d < 2) {
                        float2 pA = up2(A01), pB = up2(B01);
                        if (d == 0) { pA.x += Az0; pB.x += Bz0; }
                        else        { pA.y += Az1; pB.y += Bz1; }
                        A01 = pk2(pA.x, pA.y); B01 = pk2(pB.x, pB.y);
                    } else {
                        float2 pA = up2(A23), pB = up2(B23);
                        if (d == 2) { pA.x += Az2; pB.x += Bz2; }
                        else        { pA.y += Az3; pB.y += Bz3; }
                        A23 = pk2(pA.x, pA.y); B23 = pk2(pB.x, pB.y);
                    }
                }
                ulonglong2 sA; sA.x = A01; sA.y = A23;
                ulonglong2 sB; sB.x = B01; sB.y = B23;
                *((ulonglong2*)(oA + (size_t)i * NH)) = sA;   // STG.128 coalesced
                *((ulonglong2*)(oB + (size_t)i * NH)) = sB;
            }
        }
    }
}

// ---------------- launcher ----------------------------------------------------
extern "C" void kernel_launch(void* const* d_in, const int* in_sizes, int n_in,
                              void* d_out, int out_size) {
    const float* x    = (const float*)d_in[0];
    const float* W_ih = (const float*)d_in[1];
    const float* W_hh = (const float*)d_in[2];
    const float* b_ih = (const float*)d_in[3];
    const float* b_hh = (const float*)d_in[4];
    const float* W_y  = (const float*)d_in[5];
    const float* b_y  = (const float*)d_in[6];
    float* out = (float*)d_out;
    (void)in_sizes; (void)n_in; (void)out_size;

    const int FUSED_SMEM = 3 * NH * NH * (int)sizeof(float);   // 196608
    cudaFuncSetAttribute(k_fused, cudaFuncAttributeMaxDynamicSharedMemorySize, FUSED_SMEM);

    int prep_items = 3 * NH * NH + NB + 1;
    k_prep<<<(prep_items + 255) / 256, 256>>>(W_hh);
    k_fused<<<NBLK, 384, FUSED_SMEM>>>(x, W_ih, b_ih, W_hh, b_hh, W_y, b_y, out);
}

// round 11
// speedup vs baseline: 1.4610x; 1.4610x over previous
#include <cuda_runtime.h>
#include <cstdint>

#define NB 32
#define NS 512
#define NI 128
#define NH 128
#define NO 32
#define G3 384

typedef unsigned long long u64;

// ---------------- scratch (static device globals) -----------------------------
__device__ float  g_ih[(size_t)NS * NB * G3];       // ih[s][b][g]
__device__ float4 g_coef[(size_t)NS * NB * NH];     // {cR,cN,cZ,z} per (t,b,j)
__device__ float  g_WrT[NH * NH];                   // WrT[i][j] = W_hh[j][i]
__device__ float  g_WnT[NH * NH];                   // WnT[i][j] = W_hh[2H+j][i]
__device__ float  g_WzT[NH * NH];                   // WzT[i][j] = W_hh[H+j][i]

// ---------------- helpers ------------------------------------------------------
__device__ __forceinline__ u64 pk2(float x, float y) {
    u64 r; asm("mov.b64 %0, {%1,%2};" : "=l"(r) : "f"(x), "f"(y)); return r;
}
__device__ __forceinline__ float2 up2(u64 v) {
    float2 r; asm("mov.b64 {%0,%1}, %2;" : "=f"(r.x), "=f"(r.y) : "l"(v)); return r;
}
__device__ __forceinline__ void fma2(u64 &d, u64 a, u64 b) {
    asm("fma.rn.f32x2 %0, %1, %2, %0;" : "+l"(d) : "l"(a), "l"(b));
}
__device__ __forceinline__ u64 mul2(u64 a, u64 b) {
    u64 d; asm("mul.rn.f32x2 %0, %1, %2;" : "=l"(d) : "l"(a), "l"(b)); return d;
}
__device__ __forceinline__ void lds128(u64 &a, u64 &b, const void* p) {
    unsigned addr = (unsigned)__cvta_generic_to_shared(p);
    asm volatile("ld.shared.v2.b64 {%0,%1}, [%2];" : "=l"(a), "=l"(b) : "r"(addr));
}
__device__ __forceinline__ float sigm(float x) {
    return __fdividef(1.f, 1.f + __expf(-x));        // rcp.approx path, no div.rn
}
__device__ __forceinline__ float tanh_fast(float a) {
    float ac = fminf(fmaxf(a, -15.f), 15.f);
    float e2 = __expf(2.f * ac);
    return 1.f - __fdividef(2.f, e2 + 1.f);
}

// ---------------- K0: transpose W_hh sub-blocks --------------------------------
__global__ void k_prep(const float* __restrict__ W_hh) {
    int idx = blockIdx.x * blockDim.x + threadIdx.x;
    if (idx >= 3 * NH * NH) return;
    int m = idx / (NH * NH);
    int rem = idx - m * (NH * NH);
    int i = rem >> 7, j = rem & 127;
    int srcRow = (m == 0) ? j : ((m == 1) ? (2 * NH + j) : (NH + j));
    float v = W_hh[(size_t)srcRow * NH + i];
    if (m == 0)      g_WrT[rem] = v;
    else if (m == 1) g_WnT[rem] = v;
    else             g_WzT[rem] = v;
}

// ---------------- K1: ih = x @ W_ih^T + b_ih (W rows in registers) -------------
__global__ void __launch_bounds__(384, 1)
k_ih(const float* __restrict__ x, const float* __restrict__ W_ih,
     const float* __restrict__ b_ih) {
    __shared__ __align__(16) float sx[NI];
    int g = threadIdx.x;
    u64 w[64];
    const float2* wrow = (const float2*)(W_ih + (size_t)g * NI);
#pragma unroll
    for (int k = 0; k < 64; k++) { float2 v = wrow[k]; w[k] = pk2(v.x, v.y); }
    float bias = b_ih[g];

    for (int p = blockIdx.x; p < NS * NB; p += gridDim.x) {
        int s = p >> 5, b = p & 31;
        if (g < 32)
            ((float4*)sx)[g] = ((const float4*)(x + ((size_t)b * NS + s) * NI))[g];
        __syncthreads();
        u64 a0 = 0ull, a1 = 0ull, a2 = 0ull, a3 = 0ull;
#pragma unroll
        for (int k = 0; k < 16; k++) {
            u64 h0, h1, h2, h3;
            lds128(h0, h1, &sx[8 * k]);
            lds128(h2, h3, &sx[8 * k + 4]);
            fma2(a0, w[4 * k + 0], h0);
            fma2(a1, w[4 * k + 1], h1);
            fma2(a2, w[4 * k + 2], h2);
            fma2(a3, w[4 * k + 3], h3);
        }
        float2 f0 = up2(a0), f1 = up2(a1), f2 = up2(a2), f3 = up2(a3);
        float dot = ((f0.x + f0.y) + (f1.x + f1.y)) + ((f2.x + f2.y) + (f3.x + f3.y));
        g_ih[((size_t)s * NB + b) * G3 + g] = dot + bias;
        __syncthreads();
    }
}

// ---------------- K2: sequential GRU scan, one block per batch -----------------
__global__ void __launch_bounds__(384, 1)
k_scan(const float* __restrict__ W_hh, const float* __restrict__ b_hh,
       const float* __restrict__ W_y, const float* __restrict__ b_y,
       float* __restrict__ out) {
    __shared__ __align__(16) float sh_h[NH];
    __shared__ float sh_z[NH];
    __shared__ float sh_M[NH];
    __shared__ float sh_in[NH];
    int g = threadIdx.x;
    int b = blockIdx.x;

    u64 w[64];
    const float2* wrow = (const float2*)(W_hh + (size_t)g * NH);
#pragma unroll
    for (int k = 0; k < 64; k++) { float2 v = wrow[k]; w[k] = pk2(v.x, v.y); }
    float bias = b_hh[g];

    if (g < NH) sh_h[g] = 0.f;
    __syncthreads();

    const float* ihp = g_ih + (size_t)b * G3 + g;
    float4* coefp = g_coef + (size_t)b * NH;

    float ihv_next = __ldcg(ihp);                       // prefetch t=0
    for (int t = 0; t < NS; t++) {
        float ihv = ihv_next;
        if (t + 1 < NS) ihv_next = __ldcg(ihp + (size_t)(t + 1) * NB * G3);
        u64 a0 = 0ull, a1 = 0ull, a2 = 0ull, a3 = 0ull;
#pragma unroll
        for (int k = 0; k < 16; k++) {
            u64 h0, h1, h2, h3;
            lds128(h0, h1, &sh_h[8 * k]);
            lds128(h2, h3, &sh_h[8 * k + 4]);
            fma2(a0, w[4 * k + 0], h0);
            fma2(a1, w[4 * k + 1], h1);
            fma2(a2, w[4 * k + 2], h2);
            fma2(a3, w[4 * k + 3], h3);
        }
        float2 f0 = up2(a0), f1 = up2(a1), f2 = up2(a2), f3 = up2(a3);
        float hh = ((f0.x + f0.y) + (f1.x + f1.y)) + ((f2.x + f2.y) + (f3.x + f3.y)) + bias;
        float pre = ihv + hh;

        float r_local = 0.f;
        if (g < NH) {
            r_local = sigm(pre);
        } else if (g < 2 * NH) {
            sh_z[g - NH] = sigm(pre);
        } else {
            sh_M[g - 2 * NH]  = hh;
            sh_in[g - 2 * NH] = ihv;
        }
        __syncthreads();

        if (g < NH) {
            float r = r_local;
            float z = sh_z[g];
            float M = sh_M[g];
            float n = tanh_fast(sh_in[g] + r * M);
            float hp = sh_h[g];
            float hn = (1.f - z) * n + z * hp;
            sh_h[g] = hn;
            float c67 = (1.f - n * n) * (1.f - z);
            float4 c;
            c.x = r * (1.f - r) * M * c67;   // scales WrT
            c.y = r * c67;                   // scales WnT
            c.z = z * (1.f - z) * (hp - n);  // scales WzT
            c.w = z;                         // diagonal
            coefp[(size_t)t * NB * NH + g] = c;
        }
        __syncthreads();
    }

    if (g < NO) {
        const float* wy = W_y + (size_t)g * NH;
        float acc = b_y[g];
#pragma unroll 8
        for (int j = 0; j < NH; j++) acc += wy[j] * sh_h[j];
        out[(size_t)b * NO + g] = acc;
    }
}

// ---------------- K3: jacobian — round-9-proven pair loop, standalone ----------
// All 3 W matrices in smem (192KB). Warp-autonomous: each warp owns (t, b0/b0+1)
// tile pairs; 2 tiles amortize every W LDS.128; zero per-tile barriers.
extern __shared__ float smem3[];
__global__ void __launch_bounds__(512, 1)
k_jac(float* __restrict__ out) {
    float* sWr = smem3;
    float* sWn = smem3 + 16384;
    float* sWz = smem3 + 32768;
    int tid = threadIdx.x;
    for (int k = tid; k < NH * NH; k += 512) {
        sWr[k] = g_WrT[k];
        sWn[k] = g_WnT[k];
        sWz[k] = g_WzT[k];
    }
    __syncthreads();

    int l = tid & 31, w = tid >> 5;          // 16 warps/block
    int wg = blockIdx.x * 16 + w;            // 0..2367
    const int NPAIR = NS * NB / 2;           // 8192 pairs

    for (int pr = wg; pr < NPAIR; pr += 148 * 16) {
        int t  = pr >> 4;                    // 16 pairs per t
        int b0 = (pr & 15) << 1;             // batches b0, b0+1

        size_t q0 = (size_t)t * NB + b0;
        const float4* cpA = g_coef + q0 * NH + 4 * l;
        const float4* cpB = cpA + NH;
        float4 a0c = __ldcg(cpA + 0), a1c = __ldcg(cpA + 1);
        float4 a2c = __ldcg(cpA + 2), a3c = __ldcg(cpA + 3);
        float4 e0c = __ldcg(cpB + 0), e1c = __ldcg(cpB + 1);
        float4 e2c = __ldcg(cpB + 2), e3c = __ldcg(cpB + 3);

        u64 Acr01 = pk2(a0c.x, a1c.x), Acr23 = pk2(a2c.x, a3c.x);
        u64 Acn01 = pk2(a0c.y, a1c.y), Acn23 = pk2(a2c.y, a3c.y);
        u64 Acz01 = pk2(a0c.z, a1c.z), Acz23 = pk2(a2c.z, a3c.z);
        u64 Bcr01 = pk2(e0c.x, e1c.x), Bcr23 = pk2(e2c.x, e3c.x);
        u64 Bcn01 = pk2(e0c.y, e1c.y), Bcn23 = pk2(e2c.y, e3c.y);
        u64 Bcz01 = pk2(e0c.z, e1c.z), Bcz23 = pk2(e2c.z, e3c.z);
        float Az0 = a0c.w, Az1 = a1c.w, Az2 = a2c.w, Az3 = a3c.w;
        float Bz0 = e0c.w, Bz1 = e1c.w, Bz2 = e2c.w, Bz3 = e3c.w;

        float* oA = out + 1024 + ((size_t)(NS - 1 - t) * NB + b0) * (NH * NH) + 4 * l;
        float* oB = oA + NH * NH;

#pragma unroll 4
        for (int i = 0; i < NH; i++) {
            int idx = i * NH + 4 * l;
            u64 wr0, wr1, wn0, wn1, wz0, wz1;
            lds128(wr0, wr1, &sWr[idx]);
            lds128(wn0, wn1, &sWn[idx]);
            lds128(wz0, wz1, &sWz[idx]);

            u64 A01 = mul2(wr0, Acr01); fma2(A01, wn0, Acn01); fma2(A01, wz0, Acz01);
            u64 A23 = mul2(wr1, Acr23); fma2(A23, wn1, Acn23); fma2(A23, wz1, Acz23);
            u64 B01 = mul2(wr0, Bcr01); fma2(B01, wn0, Bcn01); fma2(B01, wz0, Bcz01);
            u64 B23 = mul2(wr1, Bcr23); fma2(B23, wn1, Bcn23); fma2(B23, wz1, Bcz23);

            if ((i >> 2) == l) {             // diagonal j == i in this lane
                int d = i & 3;
                if (d < 2) {
                    float2 pA = up2(A01), pB = up2(B01);
                    if (d == 0) { pA.x += Az0; pB.x += Bz0; }
                    else        { pA.y += Az1; pB.y += Bz1; }
                    A01 = pk2(pA.x, pA.y); B01 = pk2(pB.x, pB.y);
                } else {
                    float2 pA = up2(A23), pB = up2(B23);
                    if (d == 2) { pA.x += Az2; pB.x += Bz2; }
                    else        { pA.y += Az3; pB.y += Bz3; }
                    A23 = pk2(pA.x, pA.y); B23 = pk2(pB.x, pB.y);
                }
            }
            ulonglong2 sA; sA.x = A01; sA.y = A23;
            ulonglong2 sB; sB.x = B01; sB.y = B23;
            *((ulonglong2*)(oA + (size_t)i * NH)) = sA;   // STG.128 coalesced
            *((ulonglong2*)(oB + (size_t)i * NH)) = sB;
        }
    }
}

// ---------------- launcher ----------------------------------------------------
extern "C" void kernel_launch(void* const* d_in, const int* in_sizes, int n_in,
                              void* d_out, int out_size) {
    const float* x    = (const float*)d_in[0];
    const float* W_ih = (const float*)d_in[1];
    const float* W_hh = (const float*)d_in[2];
    const float* b_ih = (const float*)d_in[3];
    const float* b_hh = (const float*)d_in[4];
    const float* W_y  = (const float*)d_in[5];
    const float* b_y  = (const float*)d_in[6];
    float* out = (float*)d_out;
    (void)in_sizes; (void)n_in; (void)out_size;

    const int JAC_SMEM = 3 * NH * NH * (int)sizeof(float);   // 196608 B
    cudaFuncSetAttribute(k_jac, cudaFuncAttributeMaxDynamicSharedMemorySize, JAC_SMEM);

    k_prep<<<192, 256>>>(W_hh);
    k_ih<<<148, 384>>>(x, W_ih, b_ih);
    k_scan<<<NB, 384>>>(W_hh, b_hh, W_y, b_y, out);
    k_jac<<<148, 512, JAC_SMEM>>>(out);
}

// round 12
// speedup vs baseline: 1.6782x; 1.1486x over previous
#include <cuda_runtime.h>
#include <cstdint>

#define NB 32
#define NS 512
#define NI 128
#define NH 128
#define NO 32
#define G3 384
#define NJAC 116
#define NBLK (NB + NJAC)    // 148

typedef unsigned long long u64;

// ---------------- scratch (static device globals) -----------------------------
__device__ float  g_ih[(size_t)NS * NB * G3];       // ih[s][b][g]
__device__ float4 g_coef[(size_t)NS * NB * NH];     // {cR,cN,cZ,z} per (t,b,j)
__device__ float  g_WrT[NH * NH];                   // WrT[i][j] = W_hh[j][i]
__device__ float  g_WnT[NH * NH];                   // WnT[i][j] = W_hh[2H+j][i]
__device__ float  g_WzT[NH * NH];                   // WzT[i][j] = W_hh[H+j][i]
__device__ int    g_prog[NB];                       // scan progress (coarse, 4 updates)

// ---------------- helpers ------------------------------------------------------
__device__ __forceinline__ u64 pk2(float x, float y) {
    u64 r; asm("mov.b64 %0, {%1,%2};" : "=l"(r) : "f"(x), "f"(y)); return r;
}
__device__ __forceinline__ float2 up2(u64 v) {
    float2 r; asm("mov.b64 {%0,%1}, %2;" : "=f"(r.x), "=f"(r.y) : "l"(v)); return r;
}
__device__ __forceinline__ void fma2(u64 &d, u64 a, u64 b) {
    asm("fma.rn.f32x2 %0, %1, %2, %0;" : "+l"(d) : "l"(a), "l"(b));
}
__device__ __forceinline__ u64 mul2(u64 a, u64 b) {
    u64 d; asm("mul.rn.f32x2 %0, %1, %2;" : "=l"(d) : "l"(a), "l"(b)); return d;
}
__device__ __forceinline__ void lds128(u64 &a, u64 &b, const void* p) {
    unsigned addr = (unsigned)__cvta_generic_to_shared(p);
    asm volatile("ld.shared.v2.b64 {%0,%1}, [%2];" : "=l"(a), "=l"(b) : "r"(addr));
}
__device__ __forceinline__ int lda(const int* p) {   // acquire load, gpu scope
    int v; asm volatile("ld.acquire.gpu.global.s32 %0, [%1];" : "=r"(v) : "l"(p) : "memory");
    return v;
}
__device__ __forceinline__ void stv(int* p, int v) {
    asm volatile("st.volatile.global.s32 [%0], %1;" :: "l"(p), "r"(v) : "memory");
}
__device__ __forceinline__ float sigm(float x) {
    return __fdividef(1.f, 1.f + __expf(-x));
}
__device__ __forceinline__ float tanh_fast(float a) {
    // clamp-free: e2->inf => fdividef->0 => 1; e2->0 => 1-2 = -1. Exact limits.
    float e2 = __expf(2.f * a);
    return 1.f - __fdividef(2.f, e2 + 1.f);
}

// ---------------- K0: transpose W_hh + reset progress --------------------------
__global__ void k_prep(const float* __restrict__ W_hh) {
    int idx = blockIdx.x * blockDim.x + threadIdx.x;
    if (idx < 3 * NH * NH) {
        int m = idx / (NH * NH);
        int rem = idx - m * (NH * NH);
        int i = rem >> 7, j = rem & 127;
        int srcRow = (m == 0) ? j : ((m == 1) ? (2 * NH + j) : (NH + j));
        float v = W_hh[(size_t)srcRow * NH + i];
        if (m == 0)      g_WrT[rem] = v;
        else if (m == 1) g_WnT[rem] = v;
        else             g_WzT[rem] = v;
    } else if (idx - 3 * NH * NH < NB) {
        g_prog[idx - 3 * NH * NH] = 0;
    }
}

// ---------------- K1: ih = x @ W_ih^T + b_ih (unchanged, proven) ---------------
__global__ void __launch_bounds__(384, 1)
k_ih(const float* __restrict__ x, const float* __restrict__ W_ih,
     const float* __restrict__ b_ih) {
    __shared__ __align__(16) float sx[NI];
    int g = threadIdx.x;
    u64 w[64];
    const float2* wrow = (const float2*)(W_ih + (size_t)g * NI);
#pragma unroll
    for (int k = 0; k < 64; k++) { float2 v = wrow[k]; w[k] = pk2(v.x, v.y); }
    float bias = b_ih[g];

    for (int p = blockIdx.x; p < NS * NB; p += gridDim.x) {
        int s = p >> 5, b = p & 31;
        if (g < 32)
            ((float4*)sx)[g] = ((const float4*)(x + ((size_t)b * NS + s) * NI))[g];
        __syncthreads();
        u64 a0 = 0ull, a1 = 0ull, a2 = 0ull, a3 = 0ull;
#pragma unroll
        for (int k = 0; k < 16; k++) {
            u64 h0, h1, h2, h3;
            lds128(h0, h1, &sx[8 * k]);
            lds128(h2, h3, &sx[8 * k + 4]);
            fma2(a0, w[4 * k + 0], h0);
            fma2(a1, w[4 * k + 1], h1);
            fma2(a2, w[4 * k + 2], h2);
            fma2(a3, w[4 * k + 3], h3);
        }
        float2 f0 = up2(a0), f1 = up2(a1), f2 = up2(a2), f3 = up2(a3);
        float dot = ((f0.x + f0.y) + (f1.x + f1.y)) + ((f2.x + f2.y) + (f3.x + f3.y));
        g_ih[((size_t)s * NB + b) * G3 + g] = dot + bias;
        __syncthreads();
    }
}

// ---------------- K2: fused scan (32 blocks) + jacobian (116 blocks) -----------
// Sync is COARSE: scan publishes g_prog[b] only every 128 steps (4 fences total),
// so the scan critical path is untouched; jac warps consume chunks as they land.
extern __shared__ float dynsm[];   // 192KB, used by jac blocks only
__global__ void __launch_bounds__(384, 1)
k_fused2(const float* __restrict__ W_hh, const float* __restrict__ b_hh,
         const float* __restrict__ W_y,  const float* __restrict__ b_y,
         float* __restrict__ out) {
    int g = threadIdx.x;

    if (blockIdx.x < NB) {
        // ===================== SCAN (round-11 body + coarse publish) ===========
        __shared__ __align__(16) float sh_h[NH];
        __shared__ float sh_z[NH];
        __shared__ float sh_M[NH];
        __shared__ float sh_in[NH];
        int b = blockIdx.x;

        u64 w[64];
        const float2* wrow = (const float2*)(W_hh + (size_t)g * NH);
#pragma unroll
        for (int k = 0; k < 64; k++) { float2 v = wrow[k]; w[k] = pk2(v.x, v.y); }
        float bias = b_hh[g];

        if (g < NH) sh_h[g] = 0.f;
        __syncthreads();

        const float* ihp = g_ih + (size_t)b * G3 + g;
        float4* coefp = g_coef + (size_t)b * NH;

        float ihv_next = __ldcg(ihp);
        for (int t = 0; t < NS; t++) {
            float ihv = ihv_next;
            if (t + 1 < NS) ihv_next = __ldcg(ihp + (size_t)(t + 1) * NB * G3);
            u64 a0 = 0ull, a1 = 0ull, a2 = 0ull, a3 = 0ull;
#pragma unroll
            for (int k = 0; k < 16; k++) {
                u64 h0, h1, h2, h3;
                lds128(h0, h1, &sh_h[8 * k]);
                lds128(h2, h3, &sh_h[8 * k + 4]);
                fma2(a0, w[4 * k + 0], h0);
                fma2(a1, w[4 * k + 1], h1);
                fma2(a2, w[4 * k + 2], h2);
                fma2(a3, w[4 * k + 3], h3);
            }
            float2 f0 = up2(a0), f1 = up2(a1), f2 = up2(a2), f3 = up2(a3);
            float hh = ((f0.x + f0.y) + (f1.x + f1.y)) + ((f2.x + f2.y) + (f3.x + f3.y)) + bias;
            float pre = ihv + hh;

            float r_local = 0.f;
            if (g < NH) {
                r_local = sigm(pre);
            } else if (g < 2 * NH) {
                sh_z[g - NH] = sigm(pre);
            } else {
                sh_M[g - 2 * NH]  = hh;
                sh_in[g - 2 * NH] = ihv;
            }
            __syncthreads();

            if (g < NH) {
                float r = r_local;
                float z = sh_z[g];
                float M = sh_M[g];
                float n = tanh_fast(sh_in[g] + r * M);
                float hp = sh_h[g];
                float hn = (1.f - z) * n + z * hp;
                sh_h[g] = hn;
                float c67 = (1.f - n * n) * (1.f - z);
                float4 c;
                c.x = r * (1.f - r) * M * c67;
                c.y = r * c67;
                c.z = z * (1.f - z) * (hp - n);
                c.w = z;
                coefp[(size_t)t * NB * NH + g] = c;
            }
            __syncthreads();
            if (((t & 127) == 127) && g == 0) {   // 4 publishes total per batch
                __threadfence();                  // cumulative: orders all coef STGs
                stv(g_prog + b, t + 1);
            }
        }

        if (g < NO) {
            const float* wy = W_y + (size_t)g * NH;
            float acc = b_y[g];
#pragma unroll 8
            for (int j = 0; j < NH; j++) acc += wy[j] * sh_h[j];
            out[(size_t)b * NO + g] = acc;
        }
        return;
    }

    // ===================== JAC (round-11-proven pair loop + chunk wait) ========
    {
        int jid = blockIdx.x - NB;
        float* sWr = dynsm;
        float* sWn = dynsm + 16384;
        float* sWz = dynsm + 32768;
        for (int k = g; k < NH * NH; k += 384) {
            sWr[k] = g_WrT[k];
            sWn[k] = g_WnT[k];
            sWz[k] = g_WzT[k];
        }
        __syncthreads();

        int l = g & 31, w = g >> 5;          // 12 warps/block
        int wg = jid * 12 + w;               // 0..1391
        const int NPAIR = NS * NB / 2;       // 8192, t-major ascending

        for (int pr = wg; pr < NPAIR; pr += NJAC * 12) {
            int t  = pr >> 4;
            int b0 = (pr & 15) << 1;

            int need = t + 1;                // prog jumps in steps of 128
            while (lda(g_prog + b0)     < need) __nanosleep(128);
            while (lda(g_prog + b0 + 1) < need) __nanosleep(128);

            size_t q0 = (size_t)t * NB + b0;
            const float4* cpA = g_coef + q0 * NH + 4 * l;
            const float4* cpB = cpA + NH;
            float4 a0c = __ldcg(cpA + 0), a1c = __ldcg(cpA + 1);
            float4 a2c = __ldcg(cpA + 2), a3c = __ldcg(cpA + 3);
            float4 e0c = __ldcg(cpB + 0), e1c = __ldcg(cpB + 1);
            float4 e2c = __ldcg(cpB + 2), e3c = __ldcg(cpB + 3);

            u64 Acr01 = pk2(a0c.x, a1c.x), Acr23 = pk2(a2c.x, a3c.x);
            u64 Acn01 = pk2(a0c.y, a1c.y), Acn23 = pk2(a2c.y, a3c.y);
            u64 Acz01 = pk2(a0c.z, a1c.z), Acz23 = pk2(a2c.z, a3c.z);
            u64 Bcr01 = pk2(e0c.x, e1c.x), Bcr23 = pk2(e2c.x, e3c.x);
            u64 Bcn01 = pk2(e0c.y, e1c.y), Bcn23 = pk2(e2c.y, e3c.y);
            u64 Bcz01 = pk2(e0c.z, e1c.z), Bcz23 = pk2(e2c.z, e3c.z);
            float Az0 = a0c.w, Az1 = a1c.w, Az2 = a2c.w, Az3 = a3c.w;
            float Bz0 = e0c.w, Bz1 = e1c.w, Bz2 = e2c.w, Bz3 = e3c.w;

            float* oA = out + 1024 + ((size_t)(NS - 1 - t) * NB + b0) * (NH * NH) + 4 * l;
            float* oB = oA + NH * NH;

#pragma unroll 4
            for (int i = 0; i < NH; i++) {
                int idx = i * NH + 4 * l;
                u64 wr0, wr1, wn0, wn1, wz0, wz1;
                lds128(wr0, wr1, &sWr[idx]);
                lds128(wn0, wn1, &sWn[idx]);
                lds128(wz0, wz1, &sWz[idx]);

                u64 A01 = mul2(wr0, Acr01); fma2(A01, wn0, Acn01); fma2(A01, wz0, Acz01);
                u64 A23 = mul2(wr1, Acr23); fma2(A23, wn1, Acn23); fma2(A23, wz1, Acz23);
                u64 B01 = mul2(wr0, Bcr01); fma2(B01, wn0, Bcn01); fma2(B01, wz0, Bcz01);
                u64 B23 = mul2(wr1, Bcr23); fma2(B23, wn1, Bcn23); fma2(B23, wz1, Bcz23);

                if ((i >> 2) == l) {
                    int d = i & 3;
                    if (d < 2) {
                        float2 pA = up2(A01), pB = up2(B01);
                        if (d == 0) { pA.x += Az0; pB.x += Bz0; }
                        else        { pA.y += Az1; pB.y += Bz1; }
                        A01 = pk2(pA.x, pA.y); B01 = pk2(pB.x, pB.y);
                    } else {
                        float2 pA = up2(A23), pB = up2(B23);
                        if (d == 2) { pA.x += Az2; pB.x += Bz2; }
                        else        { pA.y += Az3; pB.y += Bz3; }
                        A23 = pk2(pA.x, pA.y); B23 = pk2(pB.x, pB.y);
                    }
                }
                ulonglong2 sA; sA.x = A01; sA.y = A23;
                ulonglong2 sB; sB.x = B01; sB.y = B23;
                *((ulonglong2*)(oA + (size_t)i * NH)) = sA;
                *((ulonglong2*)(oB + (size_t)i * NH)) = sB;
            }
        }
    }
}

// ---------------- launcher ----------------------------------------------------
extern "C" void kernel_launch(void* const* d_in, const int* in_sizes, int n_in,
                              void* d_out, int out_size) {
    const float* x    = (const float*)d_in[0];
    const float* W_ih = (const float*)d_in[1];
    const float* W_hh = (const float*)d_in[2];
    const float* b_ih = (const float*)d_in[3];
    const float* b_hh = (const float*)d_in[4];
    const float* W_y  = (const float*)d_in[5];
    const float* b_y  = (const float*)d_in[6];
    float* out = (float*)d_out;
    (void)in_sizes; (void)n_in; (void)out_size;

    const int FUSED_SMEM = 3 * NH * NH * (int)sizeof(float);   // 196608 B
    cudaFuncSetAttribute(k_fused2, cudaFuncAttributeMaxDynamicSharedMemorySize, FUSED_SMEM);

    k_prep<<<193, 256>>>(W_hh);
    k_ih<<<148, 384>>>(x, W_ih, b_ih);
    k_fused2<<<NBLK, 384, FUSED_SMEM>>>(W_hh, b_hh, W_y, b_y, out);
}

// round 13
// speedup vs baseline: 2.0635x; 1.2296x over previous
#include <cuda_runtime.h>
#include <cstdint>

#define NB 32
#define NS 512
#define NI 128
#define NH 128
#define NO 32
#define G3 384
#define NJAC 116
#define NBLK (NB + NJAC)    // 148

typedef unsigned long long u64;

// ---------------- scratch (static device globals) -----------------------------
__device__ float  g_ih[(size_t)NS * NB * G3];       // ih[s][b][g]
__device__ float4 g_coef[(size_t)NS * NB * NH];     // {cR,cN,cZ,z} per (t,b,j)
__device__ float  g_WrT[NH * NH];                   // WrT[i][j] = W_hh[j][i]
__device__ float  g_WnT[NH * NH];                   // WnT[i][j] = W_hh[2H+j][i]
__device__ float  g_WzT[NH * NH];                   // WzT[i][j] = W_hh[H+j][i]
__device__ int    g_prog[NB];                       // scan coef progress (coarse)
__device__ int    g_ihcnt[4];                       // ih chunk completion counters

// ---------------- helpers ------------------------------------------------------
__device__ __forceinline__ u64 pk2(float x, float y) {
    u64 r; asm("mov.b64 %0, {%1,%2};" : "=l"(r) : "f"(x), "f"(y)); return r;
}
__device__ __forceinline__ float2 up2(u64 v) {
    float2 r; asm("mov.b64 {%0,%1}, %2;" : "=f"(r.x), "=f"(r.y) : "l"(v)); return r;
}
__device__ __forceinline__ void fma2(u64 &d, u64 a, u64 b) {
    asm("fma.rn.f32x2 %0, %1, %2, %0;" : "+l"(d) : "l"(a), "l"(b));
}
__device__ __forceinline__ u64 mul2(u64 a, u64 b) {
    u64 d; asm("mul.rn.f32x2 %0, %1, %2;" : "=l"(d) : "l"(a), "l"(b)); return d;
}
__device__ __forceinline__ void lds128(u64 &a, u64 &b, const void* p) {
    unsigned addr = (unsigned)__cvta_generic_to_shared(p);
    asm volatile("ld.shared.v2.b64 {%0,%1}, [%2];" : "=l"(a), "=l"(b) : "r"(addr));
}
__device__ __forceinline__ int lda(const int* p) {   // acquire load, gpu scope
    int v; asm volatile("ld.acquire.gpu.global.s32 %0, [%1];" : "=r"(v) : "l"(p) : "memory");
    return v;
}
__device__ __forceinline__ void stv(int* p, int v) {
    asm volatile("st.volatile.global.s32 [%0], %1;" :: "l"(p), "r"(v) : "memory");
}
__device__ __forceinline__ float sigm(float x) {
    return __fdividef(1.f, 1.f + __expf(-x));
}
__device__ __forceinline__ float tanh_fast(float a) {
    // clamp-free: e2->inf => fdividef->0 => 1; e2->0 => -1. Exact limits.
    float e2 = __expf(2.f * a);
    return 1.f - __fdividef(2.f, e2 + 1.f);
}

// ---------------- K0: transpose W_hh + reset sync state ------------------------
__global__ void k_prep(const float* __restrict__ W_hh) {
    int idx = blockIdx.x * blockDim.x + threadIdx.x;
    if (idx < 3 * NH * NH) {
        int m = idx / (NH * NH);
        int rem = idx - m * (NH * NH);
        int i = rem >> 7, j = rem & 127;
        int srcRow = (m == 0) ? j : ((m == 1) ? (2 * NH + j) : (NH + j));
        float v = W_hh[(size_t)srcRow * NH + i];
        if (m == 0)      g_WrT[rem] = v;
        else if (m == 1) g_WnT[rem] = v;
        else             g_WzT[rem] = v;
    } else {
        int k = idx - 3 * NH * NH;
        if (k < NB) g_prog[k] = 0;
        else if (k < NB + 4) g_ihcnt[k - NB] = 0;
    }
}

// ---------------- fused: ih+jac (116 blocks) | scan (32 blocks) ----------------
// ih is chunked: 4 counters (one per 128-step chunk of s); scan waits only at
// chunk boundaries (4 waits total, first ~7us, rest never block).
// scan publishes coef progress every 64 steps (8 fences/batch).
extern __shared__ float dynsm[];   // 192KB: WrT | WnT | WzT (jac blocks only)
__global__ void __launch_bounds__(384, 1)
k_fused2(const float* __restrict__ x,
         const float* __restrict__ W_ih, const float* __restrict__ b_ih,
         const float* __restrict__ W_hh, const float* __restrict__ b_hh,
         const float* __restrict__ W_y,  const float* __restrict__ b_y,
         float* __restrict__ out) {
    __shared__ __align__(16) float sh_h[NH];
    __shared__ float sh_z[NH];
    __shared__ float sh_M[NH];
    __shared__ float sh_in[NH];
    __shared__ __align__(16) float sx[NI];
    int g = threadIdx.x;

    if (blockIdx.x < NB) {
        // ===================== SCAN =====================
        int b = blockIdx.x;
        u64 w[64];
        const float2* wrow = (const float2*)(W_hh + (size_t)g * NH);
#pragma unroll
        for (int k = 0; k < 64; k++) { float2 v = wrow[k]; w[k] = pk2(v.x, v.y); }
        float bias = b_hh[g];

        if (g < NH) sh_h[g] = 0.f;
        if (g == 0) { while (lda(&g_ihcnt[0]) < NJAC) __nanosleep(256); }
        __syncthreads();                     // ih chunk 0 ready + sh_h zeroed

        const float* ihp = g_ih + (size_t)b * G3 + g;
        float4* coefp = g_coef + (size_t)b * NH;

        float ihv_next = __ldcg(ihp);
        for (int t = 0; t < NS; t++) {
            float ihv = ihv_next;
            if ((t & 127) == 127 && t + 1 < NS) {      // next ih chunk ready?
                if (g == 0) {
                    int c = (t + 1) >> 7;
                    while (lda(&g_ihcnt[c]) < NJAC) __nanosleep(256);
                }
                __syncthreads();
            }
            if (t + 1 < NS) ihv_next = __ldcg(ihp + (size_t)(t + 1) * NB * G3);

            u64 a0 = 0ull, a1 = 0ull, a2 = 0ull, a3 = 0ull;
#pragma unroll
            for (int k = 0; k < 16; k++) {
                u64 h0, h1, h2, h3;
                lds128(h0, h1, &sh_h[8 * k]);
                lds128(h2, h3, &sh_h[8 * k + 4]);
                fma2(a0, w[4 * k + 0], h0);
                fma2(a1, w[4 * k + 1], h1);
                fma2(a2, w[4 * k + 2], h2);
                fma2(a3, w[4 * k + 3], h3);
            }
            float2 f0 = up2(a0), f1 = up2(a1), f2 = up2(a2), f3 = up2(a3);
            float hh = ((f0.x + f0.y) + (f1.x + f1.y)) + ((f2.x + f2.y) + (f3.x + f3.y)) + bias;
            float pre = ihv + hh;

            float r_local = 0.f;
            if (g < NH) {
                r_local = sigm(pre);
            } else if (g < 2 * NH) {
                sh_z[g - NH] = sigm(pre);
            } else {
                sh_M[g - 2 * NH]  = hh;
                sh_in[g - 2 * NH] = ihv;
            }
            __syncthreads();

            if (g < NH) {
                float r = r_local;
                float z = sh_z[g];
                float M = sh_M[g];
                float n = tanh_fast(sh_in[g] + r * M);
                float hp = sh_h[g];
                float hn = (1.f - z) * n + z * hp;
                sh_h[g] = hn;
                float c67 = (1.f - n * n) * (1.f - z);
                float4 c;
                c.x = r * (1.f - r) * M * c67;
                c.y = r * c67;
                c.z = z * (1.f - z) * (hp - n);
                c.w = z;
                coefp[(size_t)t * NB * NH + g] = c;
            }
            __syncthreads();
            if (((t & 63) == 63) && g == 0) {   // 8 publishes per batch
                __threadfence();                // cumulative: orders coef STGs
                stv(g_prog + b, t + 1);
            }
        }

        if (g < NO) {
            const float* wy = W_y + (size_t)g * NH;
            float acc = b_y[g];
#pragma unroll 8
            for (int j = 0; j < NH; j++) acc += wy[j] * sh_h[j];
            out[(size_t)b * NO + g] = acc;
        }
        return;
    }

    // ===================== IH phase (producer, chunk-counted) =====================
    int jid = blockIdx.x - NB;
    {
        u64 w[64];
        const float2* wrow = (const float2*)(W_ih + (size_t)g * NI);
#pragma unroll
        for (int k = 0; k < 64; k++) { float2 v = wrow[k]; w[k] = pk2(v.x, v.y); }
        float bias = b_ih[g];

        for (int p = jid; p < NS * NB; p += NJAC) {
            int s = p >> 5, b = p & 31;
            if (g < 32)
                ((float4*)sx)[g] = ((const float4*)(x + ((size_t)b * NS + s) * NI))[g];
            __syncthreads();
            u64 a0 = 0ull, a1 = 0ull, a2 = 0ull, a3 = 0ull;
#pragma unroll
            for (int k = 0; k < 16; k++) {
                u64 h0, h1, h2, h3;
                lds128(h0, h1, &sx[8 * k]);
                lds128(h2, h3, &sx[8 * k + 4]);
                fma2(a0, w[4 * k + 0], h0);
                fma2(a1, w[4 * k + 1], h1);
                fma2(a2, w[4 * k + 2], h2);
                fma2(a3, w[4 * k + 3], h3);
            }
            float2 f0 = up2(a0), f1 = up2(a1), f2 = up2(a2), f3 = up2(a3);
            float dot = ((f0.x + f0.y) + (f1.x + f1.y)) + ((f2.x + f2.y) + (f3.x + f3.y));
            g_ih[((size_t)s * NB + b) * G3 + g] = dot + bias;
            __syncthreads();                          // all stores of p done
            int nxt = p + NJAC;
            if ((nxt >> 12) != (p >> 12) && g == 0) { // crossed 128-step chunk
                __threadfence();
                atomicAdd(&g_ihcnt[p >> 12], 1);
            }
        }
    }

    // ===================== JAC (round-11/12-proven pair loop) =====================
    {
        float* sWr = dynsm;
        float* sWn = dynsm + 16384;
        float* sWz = dynsm + 32768;
        for (int k = g; k < NH * NH; k += 384) {
            sWr[k] = g_WrT[k];
            sWn[k] = g_WnT[k];
            sWz[k] = g_WzT[k];
        }
        __syncthreads();

        int l = g & 31, w = g >> 5;          // 12 warps/block
        int wg = jid * 12 + w;               // 0..1391
        const int NPAIR = NS * NB / 2;       // 8192, t-major ascending

        for (int pr = wg; pr < NPAIR; pr += NJAC * 12) {
            int t  = pr >> 4;
            int b0 = (pr & 15) << 1;

            int need = t + 1;                // prog advances in steps of 64
            while (lda(g_prog + b0)     < need) __nanosleep(128);
            while (lda(g_prog + b0 + 1) < need) __nanosleep(128);

            size_t q0 = (size_t)t * NB + b0;
            const float4* cpA = g_coef + q0 * NH + 4 * l;
            const float4* cpB = cpA + NH;
            float4 a0c = __ldcg(cpA + 0), a1c = __ldcg(cpA + 1);
            float4 a2c = __ldcg(cpA + 2), a3c = __ldcg(cpA + 3);
            float4 e0c = __ldcg(cpB + 0), e1c = __ldcg(cpB + 1);
            float4 e2c = __ldcg(cpB + 2), e3c = __ldcg(cpB + 3);

            u64 Acr01 = pk2(a0c.x, a1c.x), Acr23 = pk2(a2c.x, a3c.x);
            u64 Acn01 = pk2(a0c.y, a1c.y), Acn23 = pk2(a2c.y, a3c.y);
            u64 Acz01 = pk2(a0c.z, a1c.z), Acz23 = pk2(a2c.z, a3c.z);
            u64 Bcr01 = pk2(e0c.x, e1c.x), Bcr23 = pk2(e2c.x, e3c.x);
            u64 Bcn01 = pk2(e0c.y, e1c.y), Bcn23 = pk2(e2c.y, e3c.y);
            u64 Bcz01 = pk2(e0c.z, e1c.z), Bcz23 = pk2(e2c.z, e3c.z);
            float Az0 = a0c.w, Az1 = a1c.w, Az2 = a2c.w, Az3 = a3c.w;
            float Bz0 = e0c.w, Bz1 = e1c.w, Bz2 = e2c.w, Bz3 = e3c.w;

            float* oA = out + 1024 + ((size_t)(NS - 1 - t) * NB + b0) * (NH * NH) + 4 * l;
            float* oB = oA + NH * NH;

#pragma unroll 4
            for (int i = 0; i < NH; i++) {
                int idx = i * NH + 4 * l;
                u64 wr0, wr1, wn0, wn1, wz0, wz1;
                lds128(wr0, wr1, &sWr[idx]);
                lds128(wn0, wn1, &sWn[idx]);
                lds128(wz0, wz1, &sWz[idx]);

                u64 A01 = mul2(wr0, Acr01); fma2(A01, wn0, Acn01); fma2(A01, wz0, Acz01);
                u64 A23 = mul2(wr1, Acr23); fma2(A23, wn1, Acn23); fma2(A23, wz1, Acz23);
                u64 B01 = mul2(wr0, Bcr01); fma2(B01, wn0, Bcn01); fma2(B01, wz0, Bcz01);
                u64 B23 = mul2(wr1, Bcr23); fma2(B23, wn1, Bcn23); fma2(B23, wz1, Bcz23);

                if ((i >> 2) == l) {
                    int d = i & 3;
                    if (d < 2) {
                        float2 pA = up2(A01), pB = up2(B01);
                        if (d == 0) { pA.x += Az0; pB.x += Bz0; }
                        else        { pA.y += Az1; pB.y += Bz1; }
                        A01 = pk2(pA.x, pA.y); B01 = pk2(pB.x, pB.y);
                    } else {
                        float2 pA = up2(A23), pB = up2(B23);
                        if (d == 2) { pA.x += Az2; pB.x += Bz2; }
                        else        { pA.y += Az3; pB.y += Bz3; }
                        A23 = pk2(pA.x, pA.y); B23 = pk2(pB.x, pB.y);
                    }
                }
                ulonglong2 sA; sA.x = A01; sA.y = A23;
                ulonglong2 sB; sB.x = B01; sB.y = B23;
                *((ulonglong2*)(oA + (size_t)i * NH)) = sA;
                *((ulonglong2*)(oB + (size_t)i * NH)) = sB;
            }
        }
    }
}

// ---------------- launcher ----------------------------------------------------
extern "C" void kernel_launch(void* const* d_in, const int* in_sizes, int n_in,
                              void* d_out, int out_size) {
    const float* x    = (const float*)d_in[0];
    const float* W_ih = (const float*)d_in[1];
    const float* W_hh = (const float*)d_in[2];
    const float* b_ih = (const float*)d_in[3];
    const float* b_hh = (const float*)d_in[4];
    const float* W_y  = (const float*)d_in[5];
    const float* b_y  = (const float*)d_in[6];
    float* out = (float*)d_out;
    (void)in_sizes; (void)n_in; (void)out_size;

    const int FUSED_SMEM = 3 * NH * NH * (int)sizeof(float);   // 196608 B
    cudaFuncSetAttribute(k_fused2, cudaFuncAttributeMaxDynamicSharedMemorySize, FUSED_SMEM);

    k_prep<<<193, 256>>>(W_hh);
    k_fused2<<<NBLK, 384, FUSED_SMEM>>>(x, W_ih, b_ih, W_hh, b_hh, W_y, b_y, out);
}